// round 4
// baseline (speedup 1.0000x reference)
#include <cuda_runtime.h>

// ----------------------------------------------------------------------------
// SimpleVQVAE forward: enc conv3(80->512) relu conv3(512->512) -> VQ(K=1024,D=512)
//                      -> dec conv3(512->512) relu conv3(512->80)
// Activations in [B, T, C] layout. GEMM inner loop uses packed fma.rn.f32x2
// (Blackwell FFMA2): 128x128 block tile, 8x8 micro-tile, BK=16.
// ----------------------------------------------------------------------------

#define BM 128
#define BN 128
#define BK 16

typedef unsigned long long ull;

static __device__ float g_bufA[16UL * 2048 * 512];     // 64 MB
static __device__ float g_bufB[16UL * 2048 * 512];     // 64 MB
static __device__ float g_scores[32768UL * 1024];      // 128 MB
static __device__ float g_wT[3UL * 512 * 1024];        // transposed weights / codebook^T
static __device__ float g_cnorm[1024];
static __device__ int   g_idx[32768];

__device__ __forceinline__ ull ffma2(ull a, ull b, ull c) {
    ull d;
    asm("fma.rn.f32x2 %0, %1, %2, %3;" : "=l"(d) : "l"(a), "l"(b), "l"(c));
    return d;
}

// ---- weight transpose: w[CO][CI][TAPS] -> wT[TAPS][CI][CO_pad], zero pad ----
__global__ void transpose_w(const float* __restrict__ w, float* __restrict__ wT,
                            int CO, int CI, int TAPS, int CO_pad) {
    long total = (long)TAPS * CI * CO_pad;
    for (long i = (long)blockIdx.x * blockDim.x + threadIdx.x; i < total;
         i += (long)gridDim.x * blockDim.x) {
        int  co = (int)(i % CO_pad);
        long r  = i / CO_pad;
        int  ci = (int)(r % CI);
        int  k  = (int)(r / CI);
        wT[i] = (co < CO) ? w[((long)co * CI + ci) * TAPS + k] : 0.f;
    }
}

// ---- fused conv1d-as-GEMM (implicit im2col), plain GEMM when TAPS==1 -------
// y[b,t,co] = relu?( alpha * sum_{k,ci} wT[k][ci][co] * x[b, t+k-1, ci] + bias )
template <int TAPS, bool RELU, bool BIAS>
__global__ void __launch_bounds__(256)
conv_gemm(const float* __restrict__ x, const float* __restrict__ wT,
          const float* __restrict__ addvec, float* __restrict__ y,
          int T, int CI, int CO, int CO_pad, float alpha) {
    // A tile stored DUPLICATED: As2[k][m] = (v, v) so packed a-operands load directly.
    __shared__ __align__(16) float2 As2[BK][BM + 2];
    __shared__ __align__(16) float  Bs[BK][BN];

    const int t0  = blockIdx.x * BM;
    const int co0 = blockIdx.y * BN;
    const float* xb = x + (size_t)blockIdx.z * T * CI;
    float*       yb = y + (size_t)blockIdx.z * T * CO;

    const int tid = threadIdx.x;
    const int tx = tid & 15, ty = tid >> 4;          // 8x8 micro-tile coords
    const int arow = tid & 127, ahalf = tid >> 7;    // A-load: row, ci-half (8 ci each)
    const int br = tid >> 4, bc = tid & 15;          // B-load: 16 k-rows x 16 col-chunks

    ull acc2[8][4];
#pragma unroll
    for (int i = 0; i < 8; i++)
#pragma unroll
        for (int j = 0; j < 4; j++) acc2[i][j] = 0ull;

#pragma unroll
    for (int k = 0; k < TAPS; k++) {
        const int tshift = (TAPS == 1) ? 0 : (k - 1);
        for (int ci0 = 0; ci0 < CI; ci0 += BK) {
            // ---- load A tile: 128 rows x 16 ci, transposed + duplicated ----
            {
                int tg = t0 + arow + tshift;
                float4 a0 = make_float4(0.f, 0.f, 0.f, 0.f);
                float4 a1 = make_float4(0.f, 0.f, 0.f, 0.f);
                if (tg >= 0 && tg < T) {
                    const float* p = xb + (size_t)tg * CI + ci0 + ahalf * 8;
                    a0 = *reinterpret_cast<const float4*>(p);
                    a1 = *reinterpret_cast<const float4*>(p + 4);
                }
                int c = ahalf * 8;
                As2[c + 0][arow] = make_float2(a0.x, a0.x);
                As2[c + 1][arow] = make_float2(a0.y, a0.y);
                As2[c + 2][arow] = make_float2(a0.z, a0.z);
                As2[c + 3][arow] = make_float2(a0.w, a0.w);
                As2[c + 4][arow] = make_float2(a1.x, a1.x);
                As2[c + 5][arow] = make_float2(a1.y, a1.y);
                As2[c + 6][arow] = make_float2(a1.z, a1.z);
                As2[c + 7][arow] = make_float2(a1.w, a1.w);
            }
            // ---- load B tile: 16 k-rows x 128 cols (coalesced) ----
            {
                const float* wrow = wT + ((size_t)k * CI + ci0 + br) * CO_pad + co0 + bc * 8;
                *reinterpret_cast<float4*>(&Bs[br][bc * 8])     =
                    *reinterpret_cast<const float4*>(wrow);
                *reinterpret_cast<float4*>(&Bs[br][bc * 8 + 4]) =
                    *reinterpret_cast<const float4*>(wrow + 4);
            }
            __syncthreads();

#pragma unroll
            for (int kk = 0; kk < BK; kk++) {
                ull a2[8], b2[4];
                const float4* pa = reinterpret_cast<const float4*>(&As2[kk][ty * 8]);
#pragma unroll
                for (int q = 0; q < 4; q++) {
                    float4 v = pa[q];
                    a2[2 * q]     = *reinterpret_cast<ull*>(&v.x);
                    a2[2 * q + 1] = *reinterpret_cast<ull*>(&v.z);
                }
                const float4* pb = reinterpret_cast<const float4*>(&Bs[kk][tx * 8]);
#pragma unroll
                for (int q = 0; q < 2; q++) {
                    float4 v = pb[q];
                    b2[2 * q]     = *reinterpret_cast<ull*>(&v.x);
                    b2[2 * q + 1] = *reinterpret_cast<ull*>(&v.z);
                }
#pragma unroll
                for (int i = 0; i < 8; i++)
#pragma unroll
                    for (int j = 0; j < 4; j++)
                        acc2[i][j] = ffma2(a2[i], b2[j], acc2[i][j]);
            }
            __syncthreads();
        }
    }

#pragma unroll
    for (int i = 0; i < 8; i++) {
        int tg = t0 + ty * 8 + i;
        float* yrow = yb + (size_t)tg * CO;
#pragma unroll
        for (int j = 0; j < 4; j++) {
            float2 v2 = *reinterpret_cast<float2*>(&acc2[i][j]);
            int cog = co0 + tx * 8 + 2 * j;
            if (cog < CO) {
                float v = alpha * v2.x;
                if (BIAS) v += addvec[cog];
                if (RELU) v = fmaxf(v, 0.f);
                yrow[cog] = v;
            }
            if (cog + 1 < CO) {
                float v = alpha * v2.y;
                if (BIAS) v += addvec[cog + 1];
                if (RELU) v = fmaxf(v, 0.f);
                yrow[cog + 1] = v;
            }
        }
    }
}

// ---- per-codeword squared norm: cn[k] = sum_d cb[k][d]^2 (warp per row) ----
__global__ void cnorm_kernel(const float* __restrict__ cb, float* __restrict__ cn) {
    int row  = blockIdx.x * (blockDim.x >> 5) + (threadIdx.x >> 5);
    int lane = threadIdx.x & 31;
    if (row >= 1024) return;
    const float* c = cb + (size_t)row * 512;
    float s = 0.f;
    for (int i = lane; i < 512; i += 32) { float v = c[i]; s += v * v; }
#pragma unroll
    for (int o = 16; o; o >>= 1) s += __shfl_xor_sync(0xffffffffu, s, o);
    if (lane == 0) cn[row] = s;
}

// ---- argmin over 1024 (score + cnorm) per row (warp/row, first-index ties) ----
__global__ void argmin_kernel(const float* __restrict__ s, const float* __restrict__ cn,
                              int* __restrict__ idx) {
    int row  = blockIdx.x * (blockDim.x >> 5) + (threadIdx.x >> 5);
    int lane = threadIdx.x & 31;
    if (row >= 32768) return;
    const float* r = s + (size_t)row * 1024;
    float best = 3.402823466e38f;
    int   bi   = 0x7fffffff;
#pragma unroll 4
    for (int i = 0; i < 32; i++) {
        int   c = lane + (i << 5);
        float v = r[c] + cn[c];
        if (v < best || (v == best && c < bi)) { best = v; bi = c; }
    }
#pragma unroll
    for (int o = 16; o; o >>= 1) {
        float ov = __shfl_xor_sync(0xffffffffu, best, o);
        int   oi = __shfl_xor_sync(0xffffffffu, bi, o);
        if (ov < best || (ov == best && oi < bi)) { best = ov; bi = oi; }
    }
    if (lane == 0) idx[row] = bi;
}

// ---- gather codebook rows: q[n][:] = cb[idx[n]][:] -------------------------
__global__ void gather_kernel(const float* __restrict__ cb, const int* __restrict__ idx,
                              float* __restrict__ q) {
    long gid = (long)blockIdx.x * blockDim.x + threadIdx.x;   // one float4 each
    if (gid >= 32768L * 128) return;
    int n  = (int)(gid >> 7);
    int d4 = (int)(gid & 127);
    reinterpret_cast<float4*>(q)[(long)n * 128 + d4] =
        reinterpret_cast<const float4*>(cb)[(long)idx[n] * 128 + d4];
}

__global__ void idx_to_float(const int* __restrict__ idx, float* __restrict__ out, int n) {
    int i = blockIdx.x * blockDim.x + threadIdx.x;
    if (i < n) out[i] = (float)idx[i];
}

// ----------------------------------------------------------------------------
extern "C" void kernel_launch(void* const* d_in, const int* in_sizes, int n_in,
                              void* d_out, int out_size) {
    const float* mels   = (const float*)d_in[0];
    const float* enc_w1 = (const float*)d_in[1];
    const float* enc_b1 = (const float*)d_in[2];
    const float* enc_w2 = (const float*)d_in[3];
    const float* enc_b2 = (const float*)d_in[4];
    const float* cb     = (const float*)d_in[5];
    const float* dec_w1 = (const float*)d_in[6];
    const float* dec_b1 = (const float*)d_in[7];
    const float* dec_w2 = (const float*)d_in[8];
    const float* dec_b2 = (const float*)d_in[9];

    float *bufA, *bufB, *scores, *wT, *cn;
    int*   idxp;
    cudaGetSymbolAddress((void**)&bufA,   g_bufA);
    cudaGetSymbolAddress((void**)&bufB,   g_bufB);
    cudaGetSymbolAddress((void**)&scores, g_scores);
    cudaGetSymbolAddress((void**)&wT,     g_wT);
    cudaGetSymbolAddress((void**)&cn,     g_cnorm);
    cudaGetSymbolAddress((void**)&idxp,   g_idx);

    const int B = 16, T = 2048, IN = 80, H = 512, D = 512, K = 1024;
    const int BT = B * T;                 // 32768
    const int RECON = B * T * IN;         // 2621440

    // ---- encoder conv1: mels[B,T,80] -> bufA[B,T,512], relu ----
    transpose_w<<<256, 256>>>(enc_w1, wT, H, IN, 3, H);
    conv_gemm<3, true, true><<<dim3(T / BM, H / BN, B), 256>>>(
        mels, wT, enc_b1, bufA, T, IN, H, H, 1.f);

    // ---- encoder conv2: bufA -> bufB (z) ----
    transpose_w<<<256, 256>>>(enc_w2, wT, D, H, 3, D);
    conv_gemm<3, false, true><<<dim3(T / BM, D / BN, B), 256>>>(
        bufA, wT, enc_b2, bufB, T, H, D, D, 1.f);

    // ---- VQ: scores[n,k] = -2 z_n . c_k ; argmin adds ||c_k||^2 on the fly ----
    cnorm_kernel<<<1024 / 8, 256>>>(cb, cn);
    transpose_w<<<256, 256>>>(cb, wT, K, D, 1, K);            // cb^T: [D][K]
    conv_gemm<1, false, false><<<dim3(BT / BM, K / BN, 1), 256>>>(
        bufB, wT, nullptr, scores, BT, D, K, K, -2.f);
    argmin_kernel<<<BT / 8, 256>>>(scores, cn, idxp);
    gather_kernel<<<(BT * 128 + 255) / 256, 256>>>(cb, idxp, bufA);  // q -> bufA

    // ---- decoder conv1: bufA -> bufB, relu ----
    transpose_w<<<256, 256>>>(dec_w1, wT, H, D, 3, H);
    conv_gemm<3, true, true><<<dim3(T / BM, H / BN, B), 256>>>(
        bufA, wT, dec_b1, bufB, T, D, H, H, 1.f);

    // ---- decoder conv2: bufB -> recon (directly into d_out, [B,T,80]) ----
    transpose_w<<<256, 256>>>(dec_w2, wT, IN, H, 3, 128);
    float* recon = (float*)d_out;
    conv_gemm<3, false, true><<<dim3(T / BM, 1, B), 256>>>(
        bufB, wT, dec_b2, recon, T, H, IN, 128, 1.f);

    // ---- idx tail (tuple output flattened as float32), if the harness expects it ----
    if (out_size >= RECON + BT) {
        idx_to_float<<<(BT + 255) / 256, 256>>>(idxp, recon + RECON, BT);
    }
}

// round 12
// speedup vs baseline: 1.5499x; 1.5499x over previous
#include <cuda_runtime.h>
#include <cstdint>

// ----------------------------------------------------------------------------
// SimpleVQVAE forward, all GEMMs on tensor cores via mma.sync.m16n8k8.tf32
// with 3xTF32 error compensation (rel err ~1e-6, fp32-class).
// Activations in [B, T, C] layout (channel-contiguous).
// ----------------------------------------------------------------------------

static __device__ float g_bufA[16UL * 2048 * 512];     // 64 MB
static __device__ float g_bufB[16UL * 2048 * 512];     // 64 MB
static __device__ float g_scores[32768UL * 1024];      // 128 MB
static __device__ float g_wT[3UL * 512 * 1024];        // wT[k][ci][co_pad]
static __device__ float g_cnorm[1024];
static __device__ int   g_idx[32768];

__device__ __forceinline__ uint32_t f2tf32(float f) {
    uint32_t r;
    asm("cvt.rna.tf32.f32 %0, %1;" : "=r"(r) : "f"(f));
    return r;
}
__device__ __forceinline__ void split_tf32(float v, uint32_t& hi, uint32_t& lo) {
    hi = f2tf32(v);
    lo = f2tf32(v - __uint_as_float(hi));
}
__device__ __forceinline__ void mma_tf32(float* c, const uint32_t* a, const uint32_t* b) {
    asm volatile(
        "mma.sync.aligned.m16n8k8.row.col.f32.tf32.tf32.f32 "
        "{%0,%1,%2,%3}, {%4,%5,%6,%7}, {%8,%9}, {%0,%1,%2,%3};"
        : "+f"(c[0]), "+f"(c[1]), "+f"(c[2]), "+f"(c[3])
        : "r"(a[0]), "r"(a[1]), "r"(a[2]), "r"(a[3]), "r"(b[0]), "r"(b[1]));
}

// ---- weight transpose: w[CO][CI][TAPS] -> wT[TAPS][CI][CO_pad], zero pad ----
__global__ void transpose_w(const float* __restrict__ w, float* __restrict__ wT,
                            int CO, int CI, int TAPS, int CO_pad) {
    long total = (long)TAPS * CI * CO_pad;
    for (long i = (long)blockIdx.x * blockDim.x + threadIdx.x; i < total;
         i += (long)gridDim.x * blockDim.x) {
        int  co = (int)(i % CO_pad);
        long r  = i / CO_pad;
        int  ci = (int)(r % CI);
        int  k  = (int)(r / CI);
        wT[i] = (co < CO) ? w[((long)co * CI + ci) * TAPS + k] : 0.f;
    }
}

// ===================== tensor-core conv1d-as-GEMM (3xTF32) ==================
// y[b,t,co] = relu?( alpha * sum_{k,ci} wT[k][ci][co] * x[b,t+k-1,ci] + bias )
// Block: 128(M=time) x 128(N=co), BK=32, 8 warps (4M x 2N), warp tile 32x64.
#define APAD 4
#define BPAD 8
template <int TAPS, bool RELU, bool BIAS>
__global__ void __launch_bounds__(256)
conv_mma(const float* __restrict__ x, const float* __restrict__ wT,
         const float* __restrict__ addvec, float* __restrict__ y,
         int T, int CI, int CO, int CO_pad, float alpha) {
    __shared__ float As[128][32 + APAD];
    __shared__ float Bs[32][128 + BPAD];

    const int t0  = blockIdx.x * 128;
    const int co0 = blockIdx.y * 128;
    const float* xb = x + (size_t)blockIdx.z * T * CI;
    float*       yb = y + (size_t)blockIdx.z * T * CO;

    const int tid   = threadIdx.x;
    const int wid   = tid >> 5, lane = tid & 31;
    const int warpM = wid & 3, warpN = wid >> 2;           // 4 x 2 warps
    const int grp   = lane >> 2, quad = lane & 3;          // fragment coords

    float c[2][8][4];
#pragma unroll
    for (int mt = 0; mt < 2; mt++)
#pragma unroll
        for (int nt = 0; nt < 8; nt++)
#pragma unroll
            for (int r = 0; r < 4; r++) c[mt][nt][r] = 0.f;

    // NOTE: TAPS loop intentionally NOT unrolled (keeps compile size sane).
    for (int k = 0; k < TAPS; k++) {
        const int tshift = (TAPS == 1) ? 0 : (k - 1);
        for (int ci0 = 0; ci0 < CI; ci0 += 32) {
            // ---- A tile: 128 rows x 32 ci ----
            for (int i = tid; i < 1024; i += 256) {
                int row = i >> 3, kq = i & 7;
                int tg = t0 + row + tshift;
                float4 v = make_float4(0.f, 0.f, 0.f, 0.f);
                if (tg >= 0 && tg < T && ci0 + kq * 4 < CI)
                    v = *reinterpret_cast<const float4*>(xb + (size_t)tg * CI + ci0 + kq * 4);
                *reinterpret_cast<float4*>(&As[row][kq * 4]) = v;
            }
            // ---- B tile: 32 k-rows x 128 co ----
            for (int i = tid; i < 1024; i += 256) {
                int kr = i >> 5, nq = i & 31;
                float4 v = make_float4(0.f, 0.f, 0.f, 0.f);
                if (ci0 + kr < CI)
                    v = *reinterpret_cast<const float4*>(
                        wT + ((size_t)k * CI + ci0 + kr) * CO_pad + co0 + nq * 4);
                *reinterpret_cast<float4*>(&Bs[kr][nq * 4]) = v;
            }
            __syncthreads();

#pragma unroll
            for (int kk = 0; kk < 32; kk += 8) {
                uint32_t ah[2][4], al[2][4];
#pragma unroll
                for (int mt = 0; mt < 2; mt++) {
                    int m = warpM * 32 + mt * 16 + grp;
                    split_tf32(As[m][kk + quad],          ah[mt][0], al[mt][0]);
                    split_tf32(As[m + 8][kk + quad],      ah[mt][1], al[mt][1]);
                    split_tf32(As[m][kk + quad + 4],      ah[mt][2], al[mt][2]);
                    split_tf32(As[m + 8][kk + quad + 4],  ah[mt][3], al[mt][3]);
                }
#pragma unroll
                for (int nt = 0; nt < 8; nt++) {
                    int n = warpN * 64 + nt * 8 + grp;
                    uint32_t bh[2], bl[2];
                    split_tf32(Bs[kk + quad][n],     bh[0], bl[0]);
                    split_tf32(Bs[kk + quad + 4][n], bh[1], bl[1]);
#pragma unroll
                    for (int mt = 0; mt < 2; mt++) {
                        mma_tf32(c[mt][nt], ah[mt], bh);
                        mma_tf32(c[mt][nt], ah[mt], bl);
                        mma_tf32(c[mt][nt], al[mt], bh);
                    }
                }
            }
            __syncthreads();
        }
    }

    // ---- epilogue ----
#pragma unroll
    for (int mt = 0; mt < 2; mt++) {
        int r0 = t0 + warpM * 32 + mt * 16 + grp;
#pragma unroll
        for (int nt = 0; nt < 8; nt++) {
            int n = co0 + warpN * 64 + nt * 8 + 2 * quad;
#pragma unroll
            for (int half = 0; half < 2; half++) {
                int row = r0 + half * 8;
                float* yr = yb + (size_t)row * CO;
#pragma unroll
                for (int e = 0; e < 2; e++) {
                    int co = n + e;
                    if (co < CO) {
                        float v = alpha * c[mt][nt][half * 2 + e];
                        if (BIAS) v += addvec[co];
                        if (RELU) v = fmaxf(v, 0.f);
                        yr[co] = v;
                    }
                }
            }
        }
    }
}

// ======================= VQ tail kernels (fp32) =============================
__global__ void cnorm_kernel(const float* __restrict__ cb, float* __restrict__ cn) {
    int row  = blockIdx.x * (blockDim.x >> 5) + (threadIdx.x >> 5);
    int lane = threadIdx.x & 31;
    if (row >= 1024) return;
    const float* c = cb + (size_t)row * 512;
    float s = 0.f;
    for (int i = lane; i < 512; i += 32) { float v = c[i]; s += v * v; }
#pragma unroll
    for (int o = 16; o; o >>= 1) s += __shfl_xor_sync(0xffffffffu, s, o);
    if (lane == 0) cn[row] = s;
}

__global__ void argmin_kernel(const float* __restrict__ s, const float* __restrict__ cn,
                              int* __restrict__ idx) {
    int row  = blockIdx.x * (blockDim.x >> 5) + (threadIdx.x >> 5);
    int lane = threadIdx.x & 31;
    if (row >= 32768) return;
    const float* r = s + (size_t)row * 1024;
    float best = 3.402823466e38f;
    int   bi   = 0x7fffffff;
#pragma unroll 4
    for (int i = 0; i < 32; i++) {
        int   cidx = lane + (i << 5);
        float v = r[cidx] + cn[cidx];
        if (v < best || (v == best && cidx < bi)) { best = v; bi = cidx; }
    }
#pragma unroll
    for (int o = 16; o; o >>= 1) {
        float ov = __shfl_xor_sync(0xffffffffu, best, o);
        int   oi = __shfl_xor_sync(0xffffffffu, bi, o);
        if (ov < best || (ov == best && oi < bi)) { best = ov; bi = oi; }
    }
    if (lane == 0) idx[row] = bi;
}

__global__ void gather_kernel(const float* __restrict__ cb, const int* __restrict__ idx,
                              float* __restrict__ q) {
    long gid = (long)blockIdx.x * blockDim.x + threadIdx.x;
    if (gid >= 32768L * 128) return;
    int n  = (int)(gid >> 7);
    int d4 = (int)(gid & 127);
    reinterpret_cast<float4*>(q)[(long)n * 128 + d4] =
        reinterpret_cast<const float4*>(cb)[(long)idx[n] * 128 + d4];
}

__global__ void idx_to_float(const int* __restrict__ idx, float* __restrict__ out, int n) {
    int i = blockIdx.x * blockDim.x + threadIdx.x;
    if (i < n) out[i] = (float)idx[i];
}

// ----------------------------------------------------------------------------
extern "C" void kernel_launch(void* const* d_in, const int* in_sizes, int n_in,
                              void* d_out, int out_size) {
    const float* mels   = (const float*)d_in[0];
    const float* enc_w1 = (const float*)d_in[1];
    const float* enc_b1 = (const float*)d_in[2];
    const float* enc_w2 = (const float*)d_in[3];
    const float* enc_b2 = (const float*)d_in[4];
    const float* cb     = (const float*)d_in[5];
    const float* dec_w1 = (const float*)d_in[6];
    const float* dec_b1 = (const float*)d_in[7];
    const float* dec_w2 = (const float*)d_in[8];
    const float* dec_b2 = (const float*)d_in[9];

    float *bufA, *bufB, *scores, *wT, *cn;
    int*   idxp;
    cudaGetSymbolAddress((void**)&bufA,   g_bufA);
    cudaGetSymbolAddress((void**)&bufB,   g_bufB);
    cudaGetSymbolAddress((void**)&scores, g_scores);
    cudaGetSymbolAddress((void**)&wT,     g_wT);
    cudaGetSymbolAddress((void**)&cn,     g_cnorm);
    cudaGetSymbolAddress((void**)&idxp,   g_idx);

    const int B = 16, T = 2048, IN = 80, H = 512, D = 512, K = 1024;
    const int BT = B * T;
    const int RECON = B * T * IN;

    // ---- encoder conv1: mels[B,T,80] -> bufA, relu ----
    transpose_w<<<256, 256>>>(enc_w1, wT, H, IN, 3, H);
    conv_mma<3, true, true><<<dim3(T / 128, H / 128, B), 256>>>(
        mels, wT, enc_b1, bufA, T, IN, H, H, 1.f);

    // ---- encoder conv2: bufA -> bufB (z) ----
    transpose_w<<<256, 256>>>(enc_w2, wT, D, H, 3, D);
    conv_mma<3, false, true><<<dim3(T / 128, D / 128, B), 256>>>(
        bufA, wT, enc_b2, bufB, T, H, D, D, 1.f);

    // ---- VQ: scores[n,k] = -2 z_n . c_k ; argmin adds ||c_k||^2 ----
    cnorm_kernel<<<1024 / 8, 256>>>(cb, cn);
    transpose_w<<<256, 256>>>(cb, wT, K, D, 1, K);
    conv_mma<1, false, false><<<dim3(BT / 128, K / 128, 1), 256>>>(
        bufB, wT, nullptr, scores, BT, D, K, K, -2.f);
    argmin_kernel<<<BT / 8, 256>>>(scores, cn, idxp);
    gather_kernel<<<(BT * 128 + 255) / 256, 256>>>(cb, idxp, bufA);

    // ---- decoder conv1: bufA -> bufB, relu ----
    transpose_w<<<256, 256>>>(dec_w1, wT, H, D, 3, H);
    conv_mma<3, true, true><<<dim3(T / 128, H / 128, B), 256>>>(
        bufA, wT, dec_b1, bufB, T, D, H, H, 1.f);

    // ---- decoder conv2: bufB -> recon [B,T,80] (into d_out) ----
    transpose_w<<<256, 256>>>(dec_w2, wT, IN, H, 3, 128);
    float* recon = (float*)d_out;
    conv_mma<3, false, true><<<dim3(T / 128, 1, B), 256>>>(
        bufB, wT, dec_b2, recon, T, H, IN, 128, 1.f);

    if (out_size >= RECON + BT) {
        idx_to_float<<<(BT + 255) / 256, 256>>>(idxp, recon + RECON, BT);
    }
}